// round 14
// baseline (speedup 1.0000x reference)
#include <cuda_runtime.h>
#include <cstdint>
#include <cmath>

#define N0 4096
#define MASK0 (N0 - 1)
typedef unsigned long long u64;

// ---------------- static device scratch (16B-aligned for v2.u64 access) ----------------
__device__ __align__(16) u64 g_coef[(size_t)N0 * N0];     // detail coeffs, Mallat positions
__device__ __align__(16) u64 g_imgA[(size_t)2048 * 2048]; // ping
__device__ __align__(16) u64 g_imgB[(size_t)1024 * 1024]; // pong

__device__ unsigned g_bar_count;                          // zero-init; self-resetting
__device__ volatile unsigned g_bar_gen;                   // monotonic generation

__constant__ float c_lo[8] = {
    -0.010597401784997278f, 0.032883011666982945f, 0.030841381835986965f,
    -0.18703481171888114f, -0.02798376941698385f, 0.6308807679295904f,
    0.7148465705525415f, 0.23037781330885523f};

#define THRESH 0.005f

union U64F2 { u64 u; float2 f; };

__device__ __forceinline__ u64 pk2(float v) {
    u64 r; asm("mov.b64 %0, {%1, %1};" : "=l"(r) : "f"(v)); return r;
}
__device__ __forceinline__ u64 pkf2(float x, float y) {
    u64 r; asm("mov.b64 %0, {%1, %2};" : "=l"(r) : "f"(x), "f"(y)); return r;
}
__device__ __forceinline__ void fma2(u64& acc, u64 c, u64 v) {
    asm("fma.rn.f32x2 %0, %1, %2, %0;" : "+l"(acc) : "l"(c), "l"(v));
}
__device__ __forceinline__ ulonglong2 ldcg2(const u64* p) {   // 16B L2-only load
    ulonglong2 r;
    asm volatile("ld.global.cg.v2.u64 {%0,%1}, [%2];" : "=l"(r.x), "=l"(r.y) : "l"(p));
    return r;
}
__device__ __forceinline__ u64 soft2(u64 v) {
    U64F2 u; u.u = v;
    float mag = sqrtf(u.f.x * u.f.x + u.f.y * u.f.y);
    float s = (mag > THRESH) ? (1.0f - THRESH / mag) : 0.0f;
    u.f.x *= s; u.f.y *= s;
    return u.u;
}

// ---------------- shared-memory layouts (even strides: all 16B ops aligned) ----------------
struct SmemF { u64 E[38][38], O[38][38], A[38][34], D[38][34]; };   // 42.75 KB
struct SmemI { u64 LL[19][36], LH[19][36], HL[19][36], HH[19][36], Aq[19][66], Dq[19][66]; };
union SmemU { SmemF f; SmemI v; };

// ---------------- grid-wide barrier (grid sized to guaranteed residency) ----------------
__device__ __forceinline__ void grid_barrier() {
    __threadfence();
    __syncthreads();
    if (threadIdx.x == 0) {
        unsigned gen = g_bar_gen;
        if (atomicAdd(&g_bar_count, 1u) == gridDim.x - 1) {
            g_bar_count = 0;
            __threadfence();
            g_bar_gen = gen + 1;
        } else {
            while (g_bar_gen == gen) __nanosleep(64);
        }
    }
    __syncthreads();
}

// ================= forward level: H analysis + V analysis + threshold =================
// hi filters synthesized from lo via QMF: hi[k] = (-1)^k lo[7-k]
__device__ __noinline__ void fwd_level(
    const float* __restrict__ xr, const float* __restrict__ xi,
    int n, int shift, const u64* __restrict__ src, u64* __restrict__ dst,
    int thresh_all, int first, SmemF* s)
{
    const int tid = threadIdx.x;
    const int nm = n - 1;
    const int h = n >> 1, hm = h - 1;
    const int ntx = h >> 5;
    const int ntiles = ntx * (h >> 4);

    u64 lo2[8];
#pragma unroll
    for (int k = 0; k < 8; k++) lo2[k] = pk2(c_lo[k]);
    const u64 m1 = pk2(-1.0f);

    for (int t = blockIdx.x; t < ntiles; t += gridDim.x) {
        const int c0 = (t % ntx) * 32;
        const int m0 = (t / ntx) * 16;
        const int row0 = 2 * m0, col0 = 2 * c0;

        // ---- stage 1: load 38x70 input region into parity-split arrays ----
        if (first) {
            for (int idx = tid; idx < 38 * 70; idx += 256) {
                int row = idx / 70, col = idx - row * 70;
                int gr = (row0 + row) & nm, gc = (col0 + col) & nm;
                int rr = (gr - shift) & MASK0, cc = (gc - shift) & MASK0;
                u64 v = pkf2(__ldg(xr + (size_t)rr * N0 + cc),
                             __ldg(xi + (size_t)rr * N0 + cc));
                if (col & 1) s->O[row][col >> 1] = v; else s->E[row][col >> 1] = v;
            }
        } else {
            for (int idx = tid; idx < 38 * 35; idx += 256) {
                int row = idx / 35, pc = idx - row * 35;
                int gr = (row0 + row) & nm;
                int gc = (col0 + (pc << 1)) & nm;          // even
                ulonglong2 v = ldcg2(src + (size_t)gr * n + gc);
                s->E[row][pc] = v.x;
                s->O[row][pc] = v.y;
            }
        }
        __syncthreads();

        // ---- stage 2: horizontal analysis, pair-coarsened, lo-only coefficients ----
        // a[m]=sum lo[2q]E[m+q]+lo[2q+1]O[m+q];  d[m]=sum lo[7-2q]E[m+q] - sum lo[6-2q]O[m+q]
        for (int idx = tid; idx < 38 * 16; idx += 256) {
            int j = idx >> 4, u = idx & 15;
            int tt = u << 1;
            ulonglong2 e01 = *(const ulonglong2*)&s->E[j][tt];
            ulonglong2 e23 = *(const ulonglong2*)&s->E[j][tt + 2];
            u64 e4 = s->E[j][tt + 4];
            ulonglong2 o01 = *(const ulonglong2*)&s->O[j][tt];
            ulonglong2 o23 = *(const ulonglong2*)&s->O[j][tt + 2];
            u64 o4 = s->O[j][tt + 4];
            u64 e[5] = {e01.x, e01.y, e23.x, e23.y, e4};
            u64 o[5] = {o01.x, o01.y, o23.x, o23.y, o4};
            u64 a0 = 0, a1 = 0, p0 = 0, q0 = 0, p1 = 0, q1 = 0;
#pragma unroll
            for (int q = 0; q < 4; q++) {
                fma2(a0, lo2[2 * q], e[q]);     fma2(a0, lo2[2 * q + 1], o[q]);
                fma2(p0, lo2[7 - 2 * q], e[q]); fma2(q0, lo2[6 - 2 * q], o[q]);
                fma2(a1, lo2[2 * q], e[q + 1]);     fma2(a1, lo2[2 * q + 1], o[q + 1]);
                fma2(p1, lo2[7 - 2 * q], e[q + 1]); fma2(q1, lo2[6 - 2 * q], o[q + 1]);
            }
            fma2(p0, m1, q0);                              // d0 = P - Q
            fma2(p1, m1, q1);
            ulonglong2 va; va.x = a0; va.y = a1;
            ulonglong2 vd; vd.x = p0; vd.y = p1;
            *(ulonglong2*)&s->A[j][tt] = va;
            *(ulonglong2*)&s->D[j][tt] = vd;
        }
        __syncthreads();

        // ---- stage 3: vertical analysis (2-row coarsened), A phase then D phase ----
        // hl = sum_{k even} lo[7-k]rA[k] - sum_{k odd} lo[7-k]rA[k]   (same for hh on rD)
        {
            const int mc = tid & 31;
            const int mg = (tid >> 5) << 1;
            const int mcg = (c0 + mc) & hm;
            const int mA = (m0 + mg) & hm, mB = (m0 + mg + 1) & hm;

            {   // approx rows: ll (lo) + hl (hi) from A
                u64 rA[10];
#pragma unroll
                for (int w = 0; w < 10; w++) rA[w] = s->A[2 * mg + w][mc];
                u64 ll0 = 0, ll1 = 0, hp0 = 0, hq0 = 0, hp1 = 0, hq1 = 0;
#pragma unroll
                for (int k = 0; k < 8; k++) {
                    fma2(ll0, lo2[k], rA[k]);
                    fma2(ll1, lo2[k], rA[k + 2]);
                    if (k & 1) { fma2(hq0, lo2[7 - k], rA[k]); fma2(hq1, lo2[7 - k], rA[k + 2]); }
                    else       { fma2(hp0, lo2[7 - k], rA[k]); fma2(hp1, lo2[7 - k], rA[k + 2]); }
                }
                fma2(hp0, m1, hq0); fma2(hp1, m1, hq1);
                dst[(size_t)mA * h + mcg] = thresh_all ? soft2(ll0) : ll0;
                dst[(size_t)mB * h + mcg] = thresh_all ? soft2(ll1) : ll1;
                g_coef[(size_t)(mA + h) * N0 + mcg] = soft2(hp0);
                g_coef[(size_t)(mB + h) * N0 + mcg] = soft2(hp1);
            }
            {   // detail rows: lh (lo) + hh (hi) from D
                u64 rD[10];
#pragma unroll
                for (int w = 0; w < 10; w++) rD[w] = s->D[2 * mg + w][mc];
                u64 lh0 = 0, lh1 = 0, pp0 = 0, qq0 = 0, pp1 = 0, qq1 = 0;
#pragma unroll
                for (int k = 0; k < 8; k++) {
                    fma2(lh0, lo2[k], rD[k]);
                    fma2(lh1, lo2[k], rD[k + 2]);
                    if (k & 1) { fma2(qq0, lo2[7 - k], rD[k]); fma2(qq1, lo2[7 - k], rD[k + 2]); }
                    else       { fma2(pp0, lo2[7 - k], rD[k]); fma2(pp1, lo2[7 - k], rD[k + 2]); }
                }
                fma2(pp0, m1, qq0); fma2(pp1, m1, qq1);
                g_coef[(size_t)mA * N0 + h + mcg] = soft2(lh0);
                g_coef[(size_t)mB * N0 + h + mcg] = soft2(lh1);
                g_coef[(size_t)(mA + h) * N0 + h + mcg] = soft2(pp0);
                g_coef[(size_t)(mB + h) * N0 + h + mcg] = soft2(pp1);
            }
        }
        __syncthreads();
    }
}

// ================= inverse level: H synthesis + V synthesis =================
// outmode 0: scratch; 1: interleaved complex floats; 2: real plane.
__device__ __noinline__ void inv_level(
    int n, int shift, const u64* __restrict__ llsrc, u64* __restrict__ dst,
    void* outp, int outmode, size_t cap, SmemI* s)
{
    const int tid = threadIdx.x;
    const int nm = n - 1;
    const int h = n >> 1, hm = h - 1;
    const int ntx = n >> 6;
    const int ntiles = ntx * (n >> 5);

    u64 lo2[8];
#pragma unroll
    for (int k = 0; k < 8; k++) lo2[k] = pk2(c_lo[k]);
    const u64 m1 = pk2(-1.0f);

    for (int t = blockIdx.x; t < ntiles; t += gridDim.x) {
        const int j0 = (t % ntx) * 64;
        const int i0 = (t / ntx) * 32;
        const int mb = (i0 >> 1) - 3;
        const int cbm1 = (j0 >> 1) - 4;     // even column origin (cb - 1)

        // ---- stage 1: load 4 quadrants, 19 rows x 18 col-pairs, 16B ops ----
        for (int idx = tid; idx < 19 * 18; idx += 256) {
            int row = idx / 18, pc = idx - row * 18;
            int m = (mb + row) & hm;
            int mc = (cbm1 + (pc << 1)) & hm;              // even
            ulonglong2 vll = ldcg2(llsrc + (size_t)m * h + mc);
            ulonglong2 vlh = ldcg2(g_coef + (size_t)m * N0 + h + mc);
            ulonglong2 vhl = ldcg2(g_coef + (size_t)(m + h) * N0 + mc);
            ulonglong2 vhh = ldcg2(g_coef + (size_t)(m + h) * N0 + h + mc);
            *(ulonglong2*)&s->LL[row][2 * pc] = vll;
            *(ulonglong2*)&s->LH[row][2 * pc] = vlh;
            *(ulonglong2*)&s->HL[row][2 * pc] = vhl;
            *(ulonglong2*)&s->HH[row][2 * pc] = vhh;
        }
        __syncthreads();

        // ---- stage 2: horizontal synthesis, pair-coarsened, lo-only ----
        // even outputs: hi coeff = +lo[7-2q]; odd outputs: hi coeff = -lo[6-2q]
        for (int idx = tid; idx < 19 * 32; idx += 256) {
            int mrow = idx >> 5, u = idx & 31;
            u64 ae = 0, aoP = 0, aoQ = 0, de = 0, dqP = 0, dqQ = 0;
#pragma unroll
            for (int q = 0; q < 4; q++) {
                int ci = u + 4 - q;
                u64 vLL = s->LL[mrow][ci], vLH = s->LH[mrow][ci];
                u64 vHL = s->HL[mrow][ci], vHH = s->HH[mrow][ci];
                fma2(ae, lo2[2 * q], vLL);      fma2(ae, lo2[7 - 2 * q], vLH);
                fma2(aoP, lo2[2 * q + 1], vLL); fma2(aoQ, lo2[6 - 2 * q], vLH);
                fma2(de, lo2[2 * q], vHL);      fma2(de, lo2[7 - 2 * q], vHH);
                fma2(dqP, lo2[2 * q + 1], vHL); fma2(dqQ, lo2[6 - 2 * q], vHH);
            }
            fma2(aoP, m1, aoQ);
            fma2(dqP, m1, dqQ);
            ulonglong2 va; va.x = ae; va.y = aoP;
            ulonglong2 vd; vd.x = de; vd.y = dqP;
            *(ulonglong2*)&s->Aq[mrow][2 * u] = va;
            *(ulonglong2*)&s->Dq[mrow][2 * u] = vd;
        }
        __syncthreads();

        // ---- stage 3: vertical synthesis, row-pair coarsened, lo-only ----
        for (int idx = tid; idx < 512; idx += 256) {
            int jj = idx & 63, gp = idx >> 6;
            int g2 = gp << 1;
            u64 e0 = 0, e1 = 0, oA0 = 0, oD0 = 0, oA1 = 0, oD1 = 0;
#pragma unroll
            for (int w = 0; w < 5; w++) {
                u64 a = s->Aq[g2 + w][jj], d = s->Dq[g2 + w][jj];
                if (w < 4) {
                    fma2(e0, lo2[6 - 2 * w], a); fma2(e0, lo2[1 + 2 * w], d);
                    fma2(oA0, lo2[7 - 2 * w], a); fma2(oD0, lo2[2 * w], d);
                }
                if (w >= 1) {
                    fma2(e1, lo2[8 - 2 * w], a); fma2(e1, lo2[2 * w - 1], d);
                    fma2(oA1, lo2[9 - 2 * w], a); fma2(oD1, lo2[2 * w - 2], d);
                }
            }
            fma2(oA0, m1, oD0);                            // o0 = P - Q
            fma2(oA1, m1, oD1);
            const int gj = j0 + jj;
            const int r0 = i0 + (gp << 2);                 // rows r0..r0+3
            if (outmode == 0) {
                const int gjm = gj & nm;
                dst[(size_t)((r0) & nm) * n + gjm] = e0;
                dst[(size_t)((r0 + 1) & nm) * n + gjm] = oA0;
                dst[(size_t)((r0 + 2) & nm) * n + gjm] = e1;
                dst[(size_t)((r0 + 3) & nm) * n + gjm] = oA1;
            } else if (outmode == 1) {
                u64* o64 = (u64*)outp;
                int oc = (gj - shift) & MASK0;
                size_t p0 = (size_t)((r0 - shift) & MASK0) * N0 + oc;
                size_t p1 = (size_t)((r0 + 1 - shift) & MASK0) * N0 + oc;
                size_t p2 = (size_t)((r0 + 2 - shift) & MASK0) * N0 + oc;
                size_t p3 = (size_t)((r0 + 3 - shift) & MASK0) * N0 + oc;
                if (p0 < cap) o64[p0] = e0;
                if (p1 < cap) o64[p1] = oA0;
                if (p2 < cap) o64[p2] = e1;
                if (p3 < cap) o64[p3] = oA1;
            } else {
                float* of = (float*)outp;
                int oc = (gj - shift) & MASK0;
                U64F2 u0, u1, u2, u3;
                u0.u = e0; u1.u = oA0; u2.u = e1; u3.u = oA1;
                size_t p0 = (size_t)((r0 - shift) & MASK0) * N0 + oc;
                size_t p1 = (size_t)((r0 + 1 - shift) & MASK0) * N0 + oc;
                size_t p2 = (size_t)((r0 + 2 - shift) & MASK0) * N0 + oc;
                size_t p3 = (size_t)((r0 + 3 - shift) & MASK0) * N0 + oc;
                if (p0 < cap) of[p0] = u0.f.x;
                if (p1 < cap) of[p1] = u1.f.x;
                if (p2 < cap) of[p2] = u2.f.x;
                if (p3 < cap) of[p3] = u3.f.x;
            }
        }
        __syncthreads();
    }
}

// ================= single persistent kernel: all 8 phases =================
__global__ void __launch_bounds__(256, 5) wav_all(
    const float* __restrict__ xr, const float* __restrict__ xi,
    void* outp, int shift, int outmode, size_t cap)
{
    __shared__ __align__(16) SmemU sm;

    fwd_level(xr, xi, 4096, shift, nullptr, g_imgA, 0, 1, &sm.f);
    grid_barrier();
    fwd_level(xr, xi, 2048, shift, g_imgA, g_imgB, 0, 0, &sm.f);
    grid_barrier();
    fwd_level(xr, xi, 1024, shift, g_imgB, g_imgA, 0, 0, &sm.f);
    grid_barrier();
    fwd_level(xr, xi, 512, shift, g_imgA, g_imgB, 1, 0, &sm.f);
    grid_barrier();
    inv_level(512, shift, g_imgB, g_imgA, nullptr, 0, 0, &sm.v);
    grid_barrier();
    inv_level(1024, shift, g_imgA, g_imgB, nullptr, 0, 0, &sm.v);
    grid_barrier();
    inv_level(2048, shift, g_imgB, g_imgA, nullptr, 0, 0, &sm.v);
    grid_barrier();
    inv_level(4096, shift, g_imgA, nullptr, outp, outmode, cap, &sm.v);
}

// ---------------- host: numpy default_rng(1000).uniform(-3,3) ----------------
static int compute_shift() {
    const uint32_t INIT_A = 0x43b0d7e5u, MULT_A = 0x931e8875u;
    const uint32_t INIT_B = 0x8b51f9ddu, MULT_B = 0x58f38dedu;
    const uint32_t MIX_L = 0xca01f9ddu, MIX_R = 0x4973f715u;

    uint32_t hc = INIT_A;
    auto hashmix = [&](uint32_t v) -> uint32_t {
        v ^= hc; hc *= MULT_A; v *= hc; v ^= v >> 16; return v;
    };
    auto mix = [&](uint32_t x, uint32_t y) -> uint32_t {
        uint32_t r = MIX_L * x; r ^= MIX_R * y; r ^= r >> 16; return r;
    };

    uint32_t pool[4];
    for (int i = 0; i < 4; i++) pool[i] = hashmix(i == 0 ? 1000u : 0u);
    for (int s = 0; s < 4; s++)
        for (int d = 0; d < 4; d++)
            if (s != d) pool[d] = mix(pool[d], hashmix(pool[s]));

    uint32_t hb = INIT_B;
    uint32_t st[8];
    for (int i = 0; i < 8; i++) {
        uint32_t v = pool[i % 4];
        v ^= hb; hb *= MULT_B; v *= hb; v ^= v >> 16;
        st[i] = v;
    }
    uint64_t w[4];
    for (int i = 0; i < 4; i++)
        w[i] = (uint64_t)st[2 * i] | ((uint64_t)st[2 * i + 1] << 32);

    __uint128_t initstate = ((__uint128_t)w[0] << 64) | w[1];
    __uint128_t initseq = ((__uint128_t)w[2] << 64) | w[3];
    const __uint128_t MULT =
        ((__uint128_t)0x2360ed051fc65da4ULL << 64) | 0x4385df649fccf645ULL;

    __uint128_t inc = (initseq << 1) | 1;
    __uint128_t state = 0;
    state = state * MULT + inc;
    state += initstate;
    state = state * MULT + inc;
    state = state * MULT + inc;
    uint64_t xored = (uint64_t)(state >> 64) ^ (uint64_t)state;
    unsigned rot = (unsigned)(state >> 122) & 63u;
    uint64_t r64 = (xored >> rot) | (xored << ((64u - rot) & 63u));
    double dbl = (double)(r64 >> 11) * (1.0 / 9007199254740992.0);
    double u = -3.0 + 6.0 * dbl;
    return (int)nearbyint(u);
}

// ---------------- launch ----------------
extern "C" void kernel_launch(void* const* d_in, const int* in_sizes, int n_in,
                              void* d_out, int out_size) {
    if (n_in < 2) return;
    if (in_sizes[0] < N0 * N0 || in_sizes[1] < N0 * N0) return;
    const float* xr = (const float*)d_in[0];
    const float* xi = (const float*)d_in[1];

    const size_t capf = (size_t)out_size;
    const bool inter = capf >= (size_t)2 * N0 * N0;
    const int shift = compute_shift();
    const int outmode = inter ? 1 : 2;
    const size_t cap = inter ? capf / 2 : capf;   // u64 units vs float units

    // Deadlock-proof grid: exactly (resident blocks/SM) x (SM count), from the
    // driver's own occupancy calculator. Deterministic across calls.
    int perSM = 0, sms = 0, dev = 0;
    cudaGetDevice(&dev);
    cudaOccupancyMaxActiveBlocksPerMultiprocessor(&perSM, wav_all, 256, 0);
    cudaDeviceGetAttribute(&sms, cudaDevAttrMultiProcessorCount, dev);
    if (perSM < 1) perSM = 1;
    if (sms < 1) sms = 148;

    wav_all<<<perSM * sms, 256>>>(xr, xi, d_out, shift, outmode, cap);
}

// round 15
// speedup vs baseline: 1.1050x; 1.1050x over previous
#include <cuda_runtime.h>
#include <cstdint>
#include <cmath>

#define N0 4096
#define MASK0 (N0 - 1)
typedef unsigned long long u64;

// ---------------- static device scratch (16B-aligned) ----------------
__device__ __align__(16) u64 g_coef[(size_t)N0 * N0];     // detail coeffs, Mallat positions
__device__ __align__(16) u64 g_imgA[(size_t)2048 * 2048]; // ping
__device__ __align__(16) u64 g_imgB[(size_t)1024 * 1024]; // pong

__device__ unsigned g_bar_count;
__device__ volatile unsigned g_bar_gen;

__constant__ float c_lo[8] = {
    -0.010597401784997278f, 0.032883011666982945f, 0.030841381835986965f,
    -0.18703481171888114f, -0.02798376941698385f, 0.6308807679295904f,
    0.7148465705525415f, 0.23037781330885523f};
__constant__ float c_hi[8] = {
    0.23037781330885523f, -0.7148465705525415f, 0.6308807679295904f,
    0.02798376941698385f, -0.18703481171888114f, -0.030841381835986965f,
    0.032883011666982945f, 0.010597401784997278f};

#define THRESH 0.005f

// ---- dynamic smem layout (bytes) ----
// FWD: P[2] interleaved (e,o) pairs, 38 rows x 72 u64  | A,D 38 x 34
#define FWD_P1   21888
#define FWD_A    43776
#define FWD_D    54112
// INV: Q[2] = {LL,LH,HL,HH} each 19 x 36               | Aq,Dq 19 x 66
#define INV_Q1   21888
#define INV_LH   5472
#define INV_HL   10944
#define INV_HH   16416
#define INV_AQ   43776
#define INV_DQ   53808
#define DYN_SMEM 64448

union U64F2 { u64 u; float2 f; };

__device__ __forceinline__ u64 pk2(float v) {
    u64 r; asm("mov.b64 %0, {%1, %1};" : "=l"(r) : "f"(v)); return r;
}
__device__ __forceinline__ void fma2(u64& acc, u64 c, u64 v) {
    asm("fma.rn.f32x2 %0, %1, %2, %0;" : "+l"(acc) : "l"(c), "l"(v));
}
__device__ __forceinline__ void cpa16(uint32_t s, const void* g) {   // L2-only (coherence-safe)
    asm volatile("cp.async.cg.shared.global [%0], [%1], 16;" :: "r"(s), "l"(g));
}
__device__ __forceinline__ void cpa4(uint32_t s, const void* g) {    // L1 ok (immutable input)
    asm volatile("cp.async.ca.shared.global [%0], [%1], 4;" :: "r"(s), "l"(g));
}
#define CP_COMMIT() asm volatile("cp.async.commit_group;" ::: "memory")
#define CP_WAIT0()  asm volatile("cp.async.wait_group 0;" ::: "memory")

__device__ __forceinline__ u64 soft2(u64 v) {
    U64F2 u; u.u = v;
    float mag = sqrtf(u.f.x * u.f.x + u.f.y * u.f.y);
    float s = (mag > THRESH) ? (1.0f - THRESH / mag) : 0.0f;
    u.f.x *= s; u.f.y *= s;
    return u.u;
}

// ---------------- grid-wide barrier (grid sized to guaranteed residency) ----------------
__device__ __forceinline__ void grid_barrier() {
    __threadfence();
    __syncthreads();
    if (threadIdx.x == 0) {
        unsigned gen = g_bar_gen;
        if (atomicAdd(&g_bar_count, 1u) == gridDim.x - 1) {
            g_bar_count = 0;
            __threadfence();
            g_bar_gen = gen + 1;
        } else {
            while (g_bar_gen == gen) __nanosleep(64);
        }
    }
    __syncthreads();
}

// ================= forward level (cp.async double-buffered pipeline) =================
__device__ __noinline__ void fwd_level(
    const float* __restrict__ xr, const float* __restrict__ xi,
    int n, int shift, const u64* __restrict__ src, u64* __restrict__ dst,
    int thresh_all, int first, char* dynb, uint32_t smem_u32)
{
    const int tid = threadIdx.x;
    const int nm = n - 1;
    const int h = n >> 1, hm = h - 1;
    const int ntx = h >> 5;
    const int ntiles = ntx * (h >> 4);

    u64 lo2[8], hi2[8];
#pragma unroll
    for (int k = 0; k < 8; k++) { lo2[k] = pk2(c_lo[k]); hi2[k] = pk2(c_hi[k]); }

    u64* Ab = (u64*)(dynb + FWD_A);
    u64* Db = (u64*)(dynb + FWD_D);

    // prefetch tile t into buffer qb (cp.async; committed by caller)
    auto prefetch = [&](int t, int qb) {
        const int c0 = (t % ntx) * 32;
        const int m0 = (t / ntx) * 16;
        const int row0 = 2 * m0, col0 = 2 * c0;
        const uint32_t pb = smem_u32 + qb * FWD_P1;
        if (first) {
            for (int idx = tid; idx < 38 * 70; idx += 256) {
                int row = idx / 70, col = idx - row * 70;
                int gr = (row0 + row) & nm, gc = (col0 + col) & nm;
                int rr = (gr - shift) & MASK0, cc = (gc - shift) & MASK0;
                uint32_t d = pb + (uint32_t)(row * 72 + col) * 8;
                cpa4(d, xr + (size_t)rr * N0 + cc);
                cpa4(d + 4, xi + (size_t)rr * N0 + cc);
            }
        } else {
            for (int idx = tid; idx < 38 * 35; idx += 256) {
                int row = idx / 35, pc = idx - row * 35;
                int gr = (row0 + row) & nm;
                int gc = (col0 + (pc << 1)) & nm;          // even -> 16B aligned
                cpa16(pb + (uint32_t)(row * 72 + 2 * pc) * 8,
                      src + (size_t)gr * n + gc);
            }
        }
    };

    const int t0 = blockIdx.x;
    if (t0 < ntiles) prefetch(t0, 0);
    CP_COMMIT();

    int qb = 0;
    for (int t = t0; t < ntiles; t += gridDim.x, qb ^= 1) {
        CP_WAIT0();
        __syncthreads();                                   // tile t resident in P[qb]
        int tn = t + gridDim.x;
        if (tn < ntiles) prefetch(tn, qb ^ 1);             // overlaps compute below
        CP_COMMIT();

        const u64* Pb = (const u64*)(dynb + qb * FWD_P1);
        const int c0 = (t % ntx) * 32;
        const int m0 = (t / ntx) * 16;

        // ---- stage 2: horizontal analysis, pair-coarsened (16B pair loads) ----
        for (int idx = tid; idx < 38 * 16; idx += 256) {
            int j = idx >> 4, u = idx & 15;
            int tt = u << 1;
            const u64* Pr = Pb + j * 72;
            u64 e[5], o[5];
#pragma unroll
            for (int q = 0; q < 5; q++) {
                ulonglong2 v = *(const ulonglong2*)&Pr[2 * (tt + q)];
                e[q] = v.x; o[q] = v.y;
            }
            u64 a0 = 0, a1 = 0, d0 = 0, d1 = 0;
#pragma unroll
            for (int q = 0; q < 4; q++) {
                fma2(a0, lo2[2 * q], e[q]);     fma2(a0, lo2[2 * q + 1], o[q]);
                fma2(d0, hi2[2 * q], e[q]);     fma2(d0, hi2[2 * q + 1], o[q]);
                fma2(a1, lo2[2 * q], e[q + 1]); fma2(a1, lo2[2 * q + 1], o[q + 1]);
                fma2(d1, hi2[2 * q], e[q + 1]); fma2(d1, hi2[2 * q + 1], o[q + 1]);
            }
            ulonglong2 va; va.x = a0; va.y = a1;
            ulonglong2 vd; vd.x = d0; vd.y = d1;
            *(ulonglong2*)&Ab[j * 34 + tt] = va;
            *(ulonglong2*)&Db[j * 34 + tt] = vd;
        }
        __syncthreads();

        // ---- stage 3: vertical analysis (2-row coarsened), threshold, store ----
        {
            const int mc = tid & 31;
            const int mg = (tid >> 5) << 1;
            u64 rA[10], rD[10];
#pragma unroll
            for (int w = 0; w < 10; w++) {
                rA[w] = Ab[(2 * mg + w) * 34 + mc];
                rD[w] = Db[(2 * mg + w) * 34 + mc];
            }
            u64 ll0 = 0, lh0 = 0, hl0 = 0, hh0 = 0, ll1 = 0, lh1 = 0, hl1 = 0, hh1 = 0;
#pragma unroll
            for (int k = 0; k < 8; k++) {
                fma2(ll0, lo2[k], rA[k]);     fma2(hl0, hi2[k], rA[k]);
                fma2(lh0, lo2[k], rD[k]);     fma2(hh0, hi2[k], rD[k]);
                fma2(ll1, lo2[k], rA[k + 2]); fma2(hl1, hi2[k], rA[k + 2]);
                fma2(lh1, lo2[k], rD[k + 2]); fma2(hh1, hi2[k], rD[k + 2]);
            }
            const int mcg = (c0 + mc) & hm;
            const int mA = (m0 + mg) & hm, mB = (m0 + mg + 1) & hm;
            dst[(size_t)mA * h + mcg] = thresh_all ? soft2(ll0) : ll0;
            dst[(size_t)mB * h + mcg] = thresh_all ? soft2(ll1) : ll1;
            g_coef[(size_t)mA * N0 + h + mcg] = soft2(lh0);
            g_coef[(size_t)mB * N0 + h + mcg] = soft2(lh1);
            g_coef[(size_t)(mA + h) * N0 + mcg] = soft2(hl0);
            g_coef[(size_t)(mB + h) * N0 + mcg] = soft2(hl1);
            g_coef[(size_t)(mA + h) * N0 + h + mcg] = soft2(hh0);
            g_coef[(size_t)(mB + h) * N0 + h + mcg] = soft2(hh1);
        }
        __syncthreads();
    }
}

// ================= inverse level (cp.async double-buffered pipeline) =================
__device__ __noinline__ void inv_level(
    int n, int shift, const u64* __restrict__ llsrc, u64* __restrict__ dst,
    void* outp, int outmode, size_t cap, char* dynb, uint32_t smem_u32)
{
    const int tid = threadIdx.x;
    const int nm = n - 1;
    const int h = n >> 1, hm = h - 1;
    const int ntx = n >> 6;
    const int ntiles = ntx * (n >> 5);

    u64 lo2[8], hi2[8];
#pragma unroll
    for (int k = 0; k < 8; k++) { lo2[k] = pk2(c_lo[k]); hi2[k] = pk2(c_hi[k]); }

    u64* Aq = (u64*)(dynb + INV_AQ);
    u64* Dq = (u64*)(dynb + INV_DQ);

    auto prefetch = [&](int t, int qb) {
        const int j0 = (t % ntx) * 64;
        const int i0 = (t / ntx) * 32;
        const int mb = (i0 >> 1) - 3;
        const int cbm1 = (j0 >> 1) - 4;
        const uint32_t qbb = smem_u32 + qb * INV_Q1;
        for (int idx = tid; idx < 19 * 18; idx += 256) {
            int row = idx / 18, pc = idx - row * 18;
            int m = (mb + row) & hm;
            int mc = (cbm1 + (pc << 1)) & hm;              // even
            uint32_t so = (uint32_t)(row * 36 + 2 * pc) * 8;
            cpa16(qbb + so,          llsrc + (size_t)m * h + mc);
            cpa16(qbb + INV_LH + so, g_coef + (size_t)m * N0 + h + mc);
            cpa16(qbb + INV_HL + so, g_coef + (size_t)(m + h) * N0 + mc);
            cpa16(qbb + INV_HH + so, g_coef + (size_t)(m + h) * N0 + h + mc);
        }
    };

    const int t0 = blockIdx.x;
    if (t0 < ntiles) prefetch(t0, 0);
    CP_COMMIT();

    int qb = 0;
    for (int t = t0; t < ntiles; t += gridDim.x, qb ^= 1) {
        CP_WAIT0();
        __syncthreads();
        int tn = t + gridDim.x;
        if (tn < ntiles) prefetch(tn, qb ^ 1);
        CP_COMMIT();

        const u64* LLb = (const u64*)(dynb + qb * INV_Q1);
        const u64* LHb = (const u64*)(dynb + qb * INV_Q1 + INV_LH);
        const u64* HLb = (const u64*)(dynb + qb * INV_Q1 + INV_HL);
        const u64* HHb = (const u64*)(dynb + qb * INV_Q1 + INV_HH);
        const int j0 = (t % ntx) * 64;
        const int i0 = (t / ntx) * 32;

        // ---- stage 2: horizontal synthesis, pair-coarsened ----
        for (int idx = tid; idx < 19 * 32; idx += 256) {
            int mrow = idx >> 5, u = idx & 31;
            u64 ae = 0, ao = 0, de = 0, dq = 0;
#pragma unroll
            for (int q = 0; q < 4; q++) {
                int ci = mrow * 36 + u + 4 - q;
                u64 vLL = LLb[ci], vLH = LHb[ci];
                u64 vHL = HLb[ci], vHH = HHb[ci];
                fma2(ae, lo2[2 * q], vLL);     fma2(ae, hi2[2 * q], vLH);
                fma2(ao, lo2[2 * q + 1], vLL); fma2(ao, hi2[2 * q + 1], vLH);
                fma2(de, lo2[2 * q], vHL);     fma2(de, hi2[2 * q], vHH);
                fma2(dq, lo2[2 * q + 1], vHL); fma2(dq, hi2[2 * q + 1], vHH);
            }
            ulonglong2 va; va.x = ae; va.y = ao;
            ulonglong2 vd; vd.x = de; vd.y = dq;
            *(ulonglong2*)&Aq[mrow * 66 + 2 * u] = va;
            *(ulonglong2*)&Dq[mrow * 66 + 2 * u] = vd;
        }
        __syncthreads();

        // ---- stage 3: vertical synthesis, row-pair coarsened ----
        for (int idx = tid; idx < 512; idx += 256) {
            int jj = idx & 63, gp = idx >> 6;
            int g2 = gp << 1;
            u64 e0 = 0, o0 = 0, e1 = 0, o1 = 0;
#pragma unroll
            for (int w = 0; w < 5; w++) {
                u64 a = Aq[(g2 + w) * 66 + jj], d = Dq[(g2 + w) * 66 + jj];
                if (w < 4) {
                    fma2(e0, lo2[6 - 2 * w], a); fma2(e0, hi2[6 - 2 * w], d);
                    fma2(o0, lo2[7 - 2 * w], a); fma2(o0, hi2[7 - 2 * w], d);
                }
                if (w >= 1) {
                    fma2(e1, lo2[8 - 2 * w], a); fma2(e1, hi2[8 - 2 * w], d);
                    fma2(o1, lo2[9 - 2 * w], a); fma2(o1, hi2[9 - 2 * w], d);
                }
            }
            const int gj = j0 + jj;
            const int r0 = i0 + (gp << 2);
            if (outmode == 0) {
                const int gjm = gj & nm;
                dst[(size_t)((r0) & nm) * n + gjm] = e0;
                dst[(size_t)((r0 + 1) & nm) * n + gjm] = o0;
                dst[(size_t)((r0 + 2) & nm) * n + gjm] = e1;
                dst[(size_t)((r0 + 3) & nm) * n + gjm] = o1;
            } else if (outmode == 1) {
                u64* o64 = (u64*)outp;
                int oc = (gj - shift) & MASK0;
                size_t p0 = (size_t)((r0 - shift) & MASK0) * N0 + oc;
                size_t p1 = (size_t)((r0 + 1 - shift) & MASK0) * N0 + oc;
                size_t p2 = (size_t)((r0 + 2 - shift) & MASK0) * N0 + oc;
                size_t p3 = (size_t)((r0 + 3 - shift) & MASK0) * N0 + oc;
                if (p0 < cap) o64[p0] = e0;
                if (p1 < cap) o64[p1] = o0;
                if (p2 < cap) o64[p2] = e1;
                if (p3 < cap) o64[p3] = o1;
            } else {
                float* of = (float*)outp;
                int oc = (gj - shift) & MASK0;
                U64F2 u0, u1, u2, u3;
                u0.u = e0; u1.u = o0; u2.u = e1; u3.u = o1;
                size_t p0 = (size_t)((r0 - shift) & MASK0) * N0 + oc;
                size_t p1 = (size_t)((r0 + 1 - shift) & MASK0) * N0 + oc;
                size_t p2 = (size_t)((r0 + 2 - shift) & MASK0) * N0 + oc;
                size_t p3 = (size_t)((r0 + 3 - shift) & MASK0) * N0 + oc;
                if (p0 < cap) of[p0] = u0.f.x;
                if (p1 < cap) of[p1] = u1.f.x;
                if (p2 < cap) of[p2] = u2.f.x;
                if (p3 < cap) of[p3] = u3.f.x;
            }
        }
        __syncthreads();
    }
}

// ================= single persistent kernel: all 8 phases =================
__global__ void __launch_bounds__(256, 3) wav_all(
    const float* __restrict__ xr, const float* __restrict__ xi,
    void* outp, int shift, int outmode, size_t cap)
{
    extern __shared__ __align__(16) char dynb[];
    const uint32_t smem_u32 = (uint32_t)__cvta_generic_to_shared(dynb);

    fwd_level(xr, xi, 4096, shift, nullptr, g_imgA, 0, 1, dynb, smem_u32);
    grid_barrier();
    fwd_level(xr, xi, 2048, shift, g_imgA, g_imgB, 0, 0, dynb, smem_u32);
    grid_barrier();
    fwd_level(xr, xi, 1024, shift, g_imgB, g_imgA, 0, 0, dynb, smem_u32);
    grid_barrier();
    fwd_level(xr, xi, 512, shift, g_imgA, g_imgB, 1, 0, dynb, smem_u32);
    grid_barrier();
    inv_level(512, shift, g_imgB, g_imgA, nullptr, 0, 0, dynb, smem_u32);
    grid_barrier();
    inv_level(1024, shift, g_imgA, g_imgB, nullptr, 0, 0, dynb, smem_u32);
    grid_barrier();
    inv_level(2048, shift, g_imgB, g_imgA, nullptr, 0, 0, dynb, smem_u32);
    grid_barrier();
    inv_level(4096, shift, g_imgA, nullptr, outp, outmode, cap, dynb, smem_u32);
}

// ---------------- host: numpy default_rng(1000).uniform(-3,3) ----------------
static int compute_shift() {
    const uint32_t INIT_A = 0x43b0d7e5u, MULT_A = 0x931e8875u;
    const uint32_t INIT_B = 0x8b51f9ddu, MULT_B = 0x58f38dedu;
    const uint32_t MIX_L = 0xca01f9ddu, MIX_R = 0x4973f715u;

    uint32_t hc = INIT_A;
    auto hashmix = [&](uint32_t v) -> uint32_t {
        v ^= hc; hc *= MULT_A; v *= hc; v ^= v >> 16; return v;
    };
    auto mix = [&](uint32_t x, uint32_t y) -> uint32_t {
        uint32_t r = MIX_L * x; r ^= MIX_R * y; r ^= r >> 16; return r;
    };

    uint32_t pool[4];
    for (int i = 0; i < 4; i++) pool[i] = hashmix(i == 0 ? 1000u : 0u);
    for (int s = 0; s < 4; s++)
        for (int d = 0; d < 4; d++)
            if (s != d) pool[d] = mix(pool[d], hashmix(pool[s]));

    uint32_t hb = INIT_B;
    uint32_t st[8];
    for (int i = 0; i < 8; i++) {
        uint32_t v = pool[i % 4];
        v ^= hb; hb *= MULT_B; v *= hb; v ^= v >> 16;
        st[i] = v;
    }
    uint64_t w[4];
    for (int i = 0; i < 4; i++)
        w[i] = (uint64_t)st[2 * i] | ((uint64_t)st[2 * i + 1] << 32);

    __uint128_t initstate = ((__uint128_t)w[0] << 64) | w[1];
    __uint128_t initseq = ((__uint128_t)w[2] << 64) | w[3];
    const __uint128_t MULT =
        ((__uint128_t)0x2360ed051fc65da4ULL << 64) | 0x4385df649fccf645ULL;

    __uint128_t inc = (initseq << 1) | 1;
    __uint128_t state = 0;
    state = state * MULT + inc;
    state += initstate;
    state = state * MULT + inc;
    state = state * MULT + inc;
    uint64_t xored = (uint64_t)(state >> 64) ^ (uint64_t)state;
    unsigned rot = (unsigned)(state >> 122) & 63u;
    uint64_t r64 = (xored >> rot) | (xored << ((64u - rot) & 63u));
    double dbl = (double)(r64 >> 11) * (1.0 / 9007199254740992.0);
    double u = -3.0 + 6.0 * dbl;
    return (int)nearbyint(u);
}

// ---------------- launch ----------------
extern "C" void kernel_launch(void* const* d_in, const int* in_sizes, int n_in,
                              void* d_out, int out_size) {
    if (n_in < 2) return;
    if (in_sizes[0] < N0 * N0 || in_sizes[1] < N0 * N0) return;
    const float* xr = (const float*)d_in[0];
    const float* xi = (const float*)d_in[1];

    const size_t capf = (size_t)out_size;
    const bool inter = capf >= (size_t)2 * N0 * N0;
    const int shift = compute_shift();
    const int outmode = inter ? 1 : 2;
    const size_t cap = inter ? capf / 2 : capf;   // u64 units vs float units

    cudaFuncSetAttribute(wav_all, cudaFuncAttributeMaxDynamicSharedMemorySize, DYN_SMEM);

    // Deadlock-proof grid: exactly (resident blocks/SM) x (SM count).
    int perSM = 0, sms = 0, dev = 0;
    cudaGetDevice(&dev);
    cudaOccupancyMaxActiveBlocksPerMultiprocessor(&perSM, wav_all, 256, DYN_SMEM);
    cudaDeviceGetAttribute(&sms, cudaDevAttrMultiProcessorCount, dev);
    if (perSM < 1) perSM = 1;
    if (sms < 1) sms = 148;

    wav_all<<<perSM * sms, 256, DYN_SMEM>>>(xr, xi, d_out, shift, outmode, cap);
}

// round 16
// speedup vs baseline: 1.2404x; 1.1225x over previous
#include <cuda_runtime.h>
#include <cstdint>
#include <cmath>

#define N0 4096
#define MASK0 (N0 - 1)
typedef unsigned long long u64;

// ---------------- static device scratch (16B-aligned) ----------------
__device__ __align__(16) u64 g_coef[(size_t)N0 * N0];     // detail coeffs, Mallat positions
__device__ __align__(16) u64 g_imgA[(size_t)2048 * 2048]; // ping
__device__ __align__(16) u64 g_imgB[(size_t)1024 * 1024]; // pong

__device__ unsigned g_bar_count;
__device__ volatile unsigned g_bar_gen;

__constant__ float c_lo[8] = {
    -0.010597401784997278f, 0.032883011666982945f, 0.030841381835986965f,
    -0.18703481171888114f, -0.02798376941698385f, 0.6308807679295904f,
    0.7148465705525415f, 0.23037781330885523f};
__constant__ float c_hi[8] = {
    0.23037781330885523f, -0.7148465705525415f, 0.6308807679295904f,
    0.02798376941698385f, -0.18703481171888114f, -0.030841381835986965f,
    0.032883011666982945f, 0.010597401784997278f};

#define THRESH 0.005f

// ---- dynamic smem layout (bytes) ----
// FWD: P[2] interleaved (e,o) pairs, 38 rows x 72 u64  | A,D 38 x 34
#define FWD_P1   21888
#define FWD_A    43776
#define FWD_D    54112
// INV: Q[2] = {LL,LH,HL,HH} each 19 x 36               | Aq,Dq 19 x 66
#define INV_Q1   21888
#define INV_LH   5472
#define INV_HL   10944
#define INV_HH   16416
#define INV_AQ   43776
#define INV_DQ   53808
#define DYN_SMEM 64448

union U64F2 { u64 u; float2 f; };

__device__ __forceinline__ u64 pk2(float v) {
    u64 r; asm("mov.b64 %0, {%1, %1};" : "=l"(r) : "f"(v)); return r;
}
__device__ __forceinline__ void fma2(u64& acc, u64 c, u64 v) {
    asm("fma.rn.f32x2 %0, %1, %2, %0;" : "+l"(acc) : "l"(c), "l"(v));
}
__device__ __forceinline__ void cpa16(uint32_t s, const void* g) {   // L2-only (coherence-safe)
    asm volatile("cp.async.cg.shared.global [%0], [%1], 16;" :: "r"(s), "l"(g));
}
__device__ __forceinline__ void cpa4(uint32_t s, const void* g) {    // L1 ok (immutable input)
    asm volatile("cp.async.ca.shared.global [%0], [%1], 4;" :: "r"(s), "l"(g));
}
#define CP_COMMIT() asm volatile("cp.async.commit_group;" ::: "memory")
#define CP_WAIT0()  asm volatile("cp.async.wait_group 0;" ::: "memory")

// Branch-free soft threshold: s = max(1 - t*rsqrt(|v|^2), 0).
// mag<=t  <=>  1 - t*rsqrt(m2) <= 0 (monotone); m2=0 -> rsqrt=inf -> s=0.
// rsqrtf lowers to MUFU.RSQ (single instr) independent of -prec-div flags.
__device__ __forceinline__ u64 soft2(u64 v) {
    U64F2 u; u.u = v;
    float m2 = fmaf(u.f.x, u.f.x, u.f.y * u.f.y);
    float s = fmaxf(1.0f - THRESH * rsqrtf(m2), 0.0f);
    u.f.x *= s; u.f.y *= s;
    return u.u;
}

// ---------------- grid-wide barrier (grid sized to guaranteed residency) ----------------
__device__ __forceinline__ void grid_barrier() {
    __threadfence();
    __syncthreads();
    if (threadIdx.x == 0) {
        unsigned gen = g_bar_gen;
        if (atomicAdd(&g_bar_count, 1u) == gridDim.x - 1) {
            g_bar_count = 0;
            __threadfence();
            g_bar_gen = gen + 1;
        } else {
            while (g_bar_gen == gen) __nanosleep(64);
        }
    }
    __syncthreads();
}

// ================= forward level (cp.async double-buffered pipeline) =================
__device__ __noinline__ void fwd_level(
    const float* __restrict__ xr, const float* __restrict__ xi,
    int n, int shift, const u64* __restrict__ src, u64* __restrict__ dst,
    int thresh_all, int first, char* dynb, uint32_t smem_u32)
{
    const int tid = threadIdx.x;
    const int nm = n - 1;
    const int h = n >> 1, hm = h - 1;
    const int ntx = h >> 5;
    const int ntiles = ntx * (h >> 4);

    u64 lo2[8], hi2[8];
#pragma unroll
    for (int k = 0; k < 8; k++) { lo2[k] = pk2(c_lo[k]); hi2[k] = pk2(c_hi[k]); }

    u64* Ab = (u64*)(dynb + FWD_A);
    u64* Db = (u64*)(dynb + FWD_D);

    auto prefetch = [&](int t, int qb) {
        const int c0 = (t % ntx) * 32;
        const int m0 = (t / ntx) * 16;
        const int row0 = 2 * m0, col0 = 2 * c0;
        const uint32_t pb = smem_u32 + qb * FWD_P1;
        if (first) {
            for (int idx = tid; idx < 38 * 70; idx += 256) {
                int row = idx / 70, col = idx - row * 70;
                int gr = (row0 + row) & nm, gc = (col0 + col) & nm;
                int rr = (gr - shift) & MASK0, cc = (gc - shift) & MASK0;
                uint32_t d = pb + (uint32_t)(row * 72 + col) * 8;
                cpa4(d, xr + (size_t)rr * N0 + cc);
                cpa4(d + 4, xi + (size_t)rr * N0 + cc);
            }
        } else {
            for (int idx = tid; idx < 38 * 35; idx += 256) {
                int row = idx / 35, pc = idx - row * 35;
                int gr = (row0 + row) & nm;
                int gc = (col0 + (pc << 1)) & nm;          // even -> 16B aligned
                cpa16(pb + (uint32_t)(row * 72 + 2 * pc) * 8,
                      src + (size_t)gr * n + gc);
            }
        }
    };

    const int t0 = blockIdx.x;
    if (t0 < ntiles) prefetch(t0, 0);
    CP_COMMIT();

    int qb = 0;
    for (int t = t0; t < ntiles; t += gridDim.x, qb ^= 1) {
        CP_WAIT0();
        __syncthreads();                                   // tile t resident in P[qb]
        int tn = t + gridDim.x;
        if (tn < ntiles) prefetch(tn, qb ^ 1);             // overlaps compute below
        CP_COMMIT();

        const u64* Pb = (const u64*)(dynb + qb * FWD_P1);
        const int c0 = (t % ntx) * 32;
        const int m0 = (t / ntx) * 16;

        // ---- stage 2: horizontal analysis, pair-coarsened (16B pair loads) ----
        for (int idx = tid; idx < 38 * 16; idx += 256) {
            int j = idx >> 4, u = idx & 15;
            int tt = u << 1;
            const u64* Pr = Pb + j * 72;
            u64 e[5], o[5];
#pragma unroll
            for (int q = 0; q < 5; q++) {
                ulonglong2 v = *(const ulonglong2*)&Pr[2 * (tt + q)];
                e[q] = v.x; o[q] = v.y;
            }
            u64 a0 = 0, a1 = 0, d0 = 0, d1 = 0;
#pragma unroll
            for (int q = 0; q < 4; q++) {
                fma2(a0, lo2[2 * q], e[q]);     fma2(a0, lo2[2 * q + 1], o[q]);
                fma2(d0, hi2[2 * q], e[q]);     fma2(d0, hi2[2 * q + 1], o[q]);
                fma2(a1, lo2[2 * q], e[q + 1]); fma2(a1, lo2[2 * q + 1], o[q + 1]);
                fma2(d1, hi2[2 * q], e[q + 1]); fma2(d1, hi2[2 * q + 1], o[q + 1]);
            }
            ulonglong2 va; va.x = a0; va.y = a1;
            ulonglong2 vd; vd.x = d0; vd.y = d1;
            *(ulonglong2*)&Ab[j * 34 + tt] = va;
            *(ulonglong2*)&Db[j * 34 + tt] = vd;
        }
        __syncthreads();

        // ---- stage 3: vertical analysis (2-row coarsened), threshold, store ----
        {
            const int mc = tid & 31;
            const int mg = (tid >> 5) << 1;
            u64 rA[10], rD[10];
#pragma unroll
            for (int w = 0; w < 10; w++) {
                rA[w] = Ab[(2 * mg + w) * 34 + mc];
                rD[w] = Db[(2 * mg + w) * 34 + mc];
            }
            u64 ll0 = 0, lh0 = 0, hl0 = 0, hh0 = 0, ll1 = 0, lh1 = 0, hl1 = 0, hh1 = 0;
#pragma unroll
            for (int k = 0; k < 8; k++) {
                fma2(ll0, lo2[k], rA[k]);     fma2(hl0, hi2[k], rA[k]);
                fma2(lh0, lo2[k], rD[k]);     fma2(hh0, hi2[k], rD[k]);
                fma2(ll1, lo2[k], rA[k + 2]); fma2(hl1, hi2[k], rA[k + 2]);
                fma2(lh1, lo2[k], rD[k + 2]); fma2(hh1, hi2[k], rD[k + 2]);
            }
            const int mcg = (c0 + mc) & hm;
            const int mA = (m0 + mg) & hm, mB = (m0 + mg + 1) & hm;
            dst[(size_t)mA * h + mcg] = thresh_all ? soft2(ll0) : ll0;
            dst[(size_t)mB * h + mcg] = thresh_all ? soft2(ll1) : ll1;
            g_coef[(size_t)mA * N0 + h + mcg] = soft2(lh0);
            g_coef[(size_t)mB * N0 + h + mcg] = soft2(lh1);
            g_coef[(size_t)(mA + h) * N0 + mcg] = soft2(hl0);
            g_coef[(size_t)(mB + h) * N0 + mcg] = soft2(hl1);
            g_coef[(size_t)(mA + h) * N0 + h + mcg] = soft2(hh0);
            g_coef[(size_t)(mB + h) * N0 + h + mcg] = soft2(hh1);
        }
        __syncthreads();
    }
}

// ================= inverse level (cp.async double-buffered pipeline) =================
__device__ __noinline__ void inv_level(
    int n, int shift, const u64* __restrict__ llsrc, u64* __restrict__ dst,
    void* outp, int outmode, size_t cap, char* dynb, uint32_t smem_u32)
{
    const int tid = threadIdx.x;
    const int nm = n - 1;
    const int h = n >> 1, hm = h - 1;
    const int ntx = n >> 6;
    const int ntiles = ntx * (n >> 5);

    u64 lo2[8], hi2[8];
#pragma unroll
    for (int k = 0; k < 8; k++) { lo2[k] = pk2(c_lo[k]); hi2[k] = pk2(c_hi[k]); }

    u64* Aq = (u64*)(dynb + INV_AQ);
    u64* Dq = (u64*)(dynb + INV_DQ);

    auto prefetch = [&](int t, int qb) {
        const int j0 = (t % ntx) * 64;
        const int i0 = (t / ntx) * 32;
        const int mb = (i0 >> 1) - 3;
        const int cbm1 = (j0 >> 1) - 4;
        const uint32_t qbb = smem_u32 + qb * INV_Q1;
        for (int idx = tid; idx < 19 * 18; idx += 256) {
            int row = idx / 18, pc = idx - row * 18;
            int m = (mb + row) & hm;
            int mc = (cbm1 + (pc << 1)) & hm;              // even
            uint32_t so = (uint32_t)(row * 36 + 2 * pc) * 8;
            cpa16(qbb + so,          llsrc + (size_t)m * h + mc);
            cpa16(qbb + INV_LH + so, g_coef + (size_t)m * N0 + h + mc);
            cpa16(qbb + INV_HL + so, g_coef + (size_t)(m + h) * N0 + mc);
            cpa16(qbb + INV_HH + so, g_coef + (size_t)(m + h) * N0 + h + mc);
        }
    };

    const int t0 = blockIdx.x;
    if (t0 < ntiles) prefetch(t0, 0);
    CP_COMMIT();

    int qb = 0;
    for (int t = t0; t < ntiles; t += gridDim.x, qb ^= 1) {
        CP_WAIT0();
        __syncthreads();
        int tn = t + gridDim.x;
        if (tn < ntiles) prefetch(tn, qb ^ 1);
        CP_COMMIT();

        const u64* LLb = (const u64*)(dynb + qb * INV_Q1);
        const u64* LHb = (const u64*)(dynb + qb * INV_Q1 + INV_LH);
        const u64* HLb = (const u64*)(dynb + qb * INV_Q1 + INV_HL);
        const u64* HHb = (const u64*)(dynb + qb * INV_Q1 + INV_HH);
        const int j0 = (t % ntx) * 64;
        const int i0 = (t / ntx) * 32;

        // ---- stage 2: horizontal synthesis, pair-coarsened ----
        for (int idx = tid; idx < 19 * 32; idx += 256) {
            int mrow = idx >> 5, u = idx & 31;
            u64 ae = 0, ao = 0, de = 0, dq = 0;
#pragma unroll
            for (int q = 0; q < 4; q++) {
                int ci = mrow * 36 + u + 4 - q;
                u64 vLL = LLb[ci], vLH = LHb[ci];
                u64 vHL = HLb[ci], vHH = HHb[ci];
                fma2(ae, lo2[2 * q], vLL);     fma2(ae, hi2[2 * q], vLH);
                fma2(ao, lo2[2 * q + 1], vLL); fma2(ao, hi2[2 * q + 1], vLH);
                fma2(de, lo2[2 * q], vHL);     fma2(de, hi2[2 * q], vHH);
                fma2(dq, lo2[2 * q + 1], vHL); fma2(dq, hi2[2 * q + 1], vHH);
            }
            ulonglong2 va; va.x = ae; va.y = ao;
            ulonglong2 vd; vd.x = de; vd.y = dq;
            *(ulonglong2*)&Aq[mrow * 66 + 2 * u] = va;
            *(ulonglong2*)&Dq[mrow * 66 + 2 * u] = vd;
        }
        __syncthreads();

        // ---- stage 3: vertical synthesis, row-pair coarsened ----
        for (int idx = tid; idx < 512; idx += 256) {
            int jj = idx & 63, gp = idx >> 6;
            int g2 = gp << 1;
            u64 e0 = 0, o0 = 0, e1 = 0, o1 = 0;
#pragma unroll
            for (int w = 0; w < 5; w++) {
                u64 a = Aq[(g2 + w) * 66 + jj], d = Dq[(g2 + w) * 66 + jj];
                if (w < 4) {
                    fma2(e0, lo2[6 - 2 * w], a); fma2(e0, hi2[6 - 2 * w], d);
                    fma2(o0, lo2[7 - 2 * w], a); fma2(o0, hi2[7 - 2 * w], d);
                }
                if (w >= 1) {
                    fma2(e1, lo2[8 - 2 * w], a); fma2(e1, hi2[8 - 2 * w], d);
                    fma2(o1, lo2[9 - 2 * w], a); fma2(o1, hi2[9 - 2 * w], d);
                }
            }
            const int gj = j0 + jj;
            const int r0 = i0 + (gp << 2);
            if (outmode == 0) {
                const int gjm = gj & nm;
                dst[(size_t)((r0) & nm) * n + gjm] = e0;
                dst[(size_t)((r0 + 1) & nm) * n + gjm] = o0;
                dst[(size_t)((r0 + 2) & nm) * n + gjm] = e1;
                dst[(size_t)((r0 + 3) & nm) * n + gjm] = o1;
            } else if (outmode == 1) {
                u64* o64 = (u64*)outp;
                int oc = (gj - shift) & MASK0;
                size_t p0 = (size_t)((r0 - shift) & MASK0) * N0 + oc;
                size_t p1 = (size_t)((r0 + 1 - shift) & MASK0) * N0 + oc;
                size_t p2 = (size_t)((r0 + 2 - shift) & MASK0) * N0 + oc;
                size_t p3 = (size_t)((r0 + 3 - shift) & MASK0) * N0 + oc;
                if (p0 < cap) o64[p0] = e0;
                if (p1 < cap) o64[p1] = o0;
                if (p2 < cap) o64[p2] = e1;
                if (p3 < cap) o64[p3] = o1;
            } else {
                float* of = (float*)outp;
                int oc = (gj - shift) & MASK0;
                U64F2 u0, u1, u2, u3;
                u0.u = e0; u1.u = o0; u2.u = e1; u3.u = o1;
                size_t p0 = (size_t)((r0 - shift) & MASK0) * N0 + oc;
                size_t p1 = (size_t)((r0 + 1 - shift) & MASK0) * N0 + oc;
                size_t p2 = (size_t)((r0 + 2 - shift) & MASK0) * N0 + oc;
                size_t p3 = (size_t)((r0 + 3 - shift) & MASK0) * N0 + oc;
                if (p0 < cap) of[p0] = u0.f.x;
                if (p1 < cap) of[p1] = u1.f.x;
                if (p2 < cap) of[p2] = u2.f.x;
                if (p3 < cap) of[p3] = u3.f.x;
            }
        }
        __syncthreads();
    }
}

// ================= single persistent kernel: all 8 phases =================
__global__ void __launch_bounds__(256, 3) wav_all(
    const float* __restrict__ xr, const float* __restrict__ xi,
    void* outp, int shift, int outmode, size_t cap)
{
    extern __shared__ __align__(16) char dynb[];
    const uint32_t smem_u32 = (uint32_t)__cvta_generic_to_shared(dynb);

    fwd_level(xr, xi, 4096, shift, nullptr, g_imgA, 0, 1, dynb, smem_u32);
    grid_barrier();
    fwd_level(xr, xi, 2048, shift, g_imgA, g_imgB, 0, 0, dynb, smem_u32);
    grid_barrier();
    fwd_level(xr, xi, 1024, shift, g_imgB, g_imgA, 0, 0, dynb, smem_u32);
    grid_barrier();
    fwd_level(xr, xi, 512, shift, g_imgA, g_imgB, 1, 0, dynb, smem_u32);
    grid_barrier();
    inv_level(512, shift, g_imgB, g_imgA, nullptr, 0, 0, dynb, smem_u32);
    grid_barrier();
    inv_level(1024, shift, g_imgA, g_imgB, nullptr, 0, 0, dynb, smem_u32);
    grid_barrier();
    inv_level(2048, shift, g_imgB, g_imgA, nullptr, 0, 0, dynb, smem_u32);
    grid_barrier();
    inv_level(4096, shift, g_imgA, nullptr, outp, outmode, cap, dynb, smem_u32);
}

// ---------------- host: numpy default_rng(1000).uniform(-3,3) ----------------
static int compute_shift() {
    const uint32_t INIT_A = 0x43b0d7e5u, MULT_A = 0x931e8875u;
    const uint32_t INIT_B = 0x8b51f9ddu, MULT_B = 0x58f38dedu;
    const uint32_t MIX_L = 0xca01f9ddu, MIX_R = 0x4973f715u;

    uint32_t hc = INIT_A;
    auto hashmix = [&](uint32_t v) -> uint32_t {
        v ^= hc; hc *= MULT_A; v *= hc; v ^= v >> 16; return v;
    };
    auto mix = [&](uint32_t x, uint32_t y) -> uint32_t {
        uint32_t r = MIX_L * x; r ^= MIX_R * y; r ^= r >> 16; return r;
    };

    uint32_t pool[4];
    for (int i = 0; i < 4; i++) pool[i] = hashmix(i == 0 ? 1000u : 0u);
    for (int s = 0; s < 4; s++)
        for (int d = 0; d < 4; d++)
            if (s != d) pool[d] = mix(pool[d], hashmix(pool[s]));

    uint32_t hb = INIT_B;
    uint32_t st[8];
    for (int i = 0; i < 8; i++) {
        uint32_t v = pool[i % 4];
        v ^= hb; hb *= MULT_B; v *= hb; v ^= v >> 16;
        st[i] = v;
    }
    uint64_t w[4];
    for (int i = 0; i < 4; i++)
        w[i] = (uint64_t)st[2 * i] | ((uint64_t)st[2 * i + 1] << 32);

    __uint128_t initstate = ((__uint128_t)w[0] << 64) | w[1];
    __uint128_t initseq = ((__uint128_t)w[2] << 64) | w[3];
    const __uint128_t MULT =
        ((__uint128_t)0x2360ed051fc65da4ULL << 64) | 0x4385df649fccf645ULL;

    __uint128_t inc = (initseq << 1) | 1;
    __uint128_t state = 0;
    state = state * MULT + inc;
    state += initstate;
    state = state * MULT + inc;
    state = state * MULT + inc;
    uint64_t xored = (uint64_t)(state >> 64) ^ (uint64_t)state;
    unsigned rot = (unsigned)(state >> 122) & 63u;
    uint64_t r64 = (xored >> rot) | (xored << ((64u - rot) & 63u));
    double dbl = (double)(r64 >> 11) * (1.0 / 9007199254740992.0);
    double u = -3.0 + 6.0 * dbl;
    return (int)nearbyint(u);
}

// ---------------- launch ----------------
extern "C" void kernel_launch(void* const* d_in, const int* in_sizes, int n_in,
                              void* d_out, int out_size) {
    if (n_in < 2) return;
    if (in_sizes[0] < N0 * N0 || in_sizes[1] < N0 * N0) return;
    const float* xr = (const float*)d_in[0];
    const float* xi = (const float*)d_in[1];

    const size_t capf = (size_t)out_size;
    const bool inter = capf >= (size_t)2 * N0 * N0;
    const int shift = compute_shift();
    const int outmode = inter ? 1 : 2;
    const size_t cap = inter ? capf / 2 : capf;   // u64 units vs float units

    cudaFuncSetAttribute(wav_all, cudaFuncAttributeMaxDynamicSharedMemorySize, DYN_SMEM);

    // Deadlock-proof grid: exactly (resident blocks/SM) x (SM count).
    int perSM = 0, sms = 0, dev = 0;
    cudaGetDevice(&dev);
    cudaOccupancyMaxActiveBlocksPerMultiprocessor(&perSM, wav_all, 256, DYN_SMEM);
    cudaDeviceGetAttribute(&sms, cudaDevAttrMultiProcessorCount, dev);
    if (perSM < 1) perSM = 1;
    if (sms < 1) sms = 148;

    wav_all<<<perSM * sms, 256, DYN_SMEM>>>(xr, xi, d_out, shift, outmode, cap);
}